// round 9
// baseline (speedup 1.0000x reference)
#include <cuda_runtime.h>

#define MN   1024
#define HID  64
#define TJ   128
#define TSTR 68          // row stride (floats): 64 + 4 pad ; 272 B = 17*16 -> float4-aligned rows
#define DYN_FLOATS (4096 + 4096 + TJ*TSTR + TJ*TSTR)
#define DYN_BYTES  (DYN_FLOATS * 4)

__device__ float g_pei[MN * HID];   // includes be1
__device__ float g_pej[MN * HID];

__device__ __forceinline__ float fsilu(float v) {
    return __fdividef(v, 1.0f + __expf(-v));
}

// ---- packed fp32x2 helpers (sm_103a) --------------------------------------
union F2U { unsigned long long u; float2 f; };

__device__ __forceinline__ unsigned long long ffma2(unsigned long long a,
                                                    unsigned long long b,
                                                    unsigned long long c) {
    unsigned long long d;
    asm("fma.rn.f32x2 %0, %1, %2, %3;" : "=l"(d) : "l"(a), "l"(b), "l"(c));
    return d;
}
__device__ __forceinline__ unsigned long long pack2(float v) {
    unsigned long long d;
    asm("mov.b64 %0, {%1, %1};" : "=l"(d) : "f"(v));
    return d;
}

// ---------------------------------------------------------------------------
// Precompute: pei[i][c] = be1[c] + sum_k h[i][k]*We1[k][c]
//             pej[j][c] =          sum_k h[j][k]*We1[64+k][c]
// ---------------------------------------------------------------------------
__global__ void pre_kernel(const float* __restrict__ h,
                           const float* __restrict__ We1,
                           const float* __restrict__ be1) {
    __shared__ float hs[4][64];
    const int tid = threadIdx.x;
    const int rr  = tid >> 6;
    const int c   = tid & 63;
    const int row = blockIdx.x * 4 + rr;
    hs[rr][c] = h[row * 64 + c];
    __syncthreads();
    float ai = be1[c];
    float aj = 0.f;
#pragma unroll 8
    for (int k = 0; k < 64; k++) {
        const float hv = hs[rr][k];
        ai += hv * We1[k * 64 + c];
        aj += hv * We1[(64 + k) * 64 + c];
    }
    g_pei[row * 64 + c] = ai;
    g_pej[row * 64 + c] = aj;
}

// 128x64x64 GEMM micro-kernel using packed f32x2 FMA.
// Thread owns rows {rg, rg+32, rg+64, rg+96} (strided -> conflict-free A LDS)
// and SPLIT column set {cg*4..+3, cg*4+32..+35} (conflict-free B LDS + stores):
//   acc[q][0] = cols (4cg, 4cg+1)     acc[q][1] = (4cg+2, 4cg+3)
//   acc[q][2] = (4cg+32, 4cg+33)      acc[q][3] = (4cg+34, 4cg+35)
__device__ __forceinline__ void gemm_tile(const float* __restrict__ Arow0,  // A + rg*TSTR
                                          const float* __restrict__ Bs,     // [64][64] row-major
                                          int cg, float2 acc[4][4]) {
    unsigned long long a2[4][4];
#pragma unroll
    for (int q = 0; q < 4; q++)
#pragma unroll
        for (int p = 0; p < 4; p++) a2[q][p] = 0ull;

#pragma unroll 4
    for (int k4 = 0; k4 < 16; k4++) {
        const int k = k4 * 4;
        // A: 4 rows (stride 32*TSTR) x 4 k-values, via LDS.128
        float4 af[4];
        af[0] = *(const float4*)(Arow0 + k);
        af[1] = *(const float4*)(Arow0 + 32 * TSTR + k);
        af[2] = *(const float4*)(Arow0 + 64 * TSTR + k);
        af[3] = *(const float4*)(Arow0 + 96 * TSTR + k);
#pragma unroll
        for (int kk = 0; kk < 4; kk++) {
            unsigned long long ap[4];
            ap[0] = pack2(((const float*)&af[0])[kk]);
            ap[1] = pack2(((const float*)&af[1])[kk]);
            ap[2] = pack2(((const float*)&af[2])[kk]);
            ap[3] = pack2(((const float*)&af[3])[kk]);
            const ulonglong2 b0 = *(const ulonglong2*)(Bs + (k + kk) * 64 + cg * 4);
            const ulonglong2 b1 = *(const ulonglong2*)(Bs + (k + kk) * 64 + cg * 4 + 32);
            const unsigned long long bv[4] = {b0.x, b0.y, b1.x, b1.y};
#pragma unroll
            for (int q = 0; q < 4; q++)
#pragma unroll
                for (int p = 0; p < 4; p++) a2[q][p] = ffma2(ap[q], bv[p], a2[q][p]);
        }
    }
#pragma unroll
    for (int q = 0; q < 4; q++)
#pragma unroll
        for (int p = 0; p < 4; p++) {
            F2U u; u.u = a2[q][p];
            acc[q][p] = u.f;
        }
}

// ---------------------------------------------------------------------------
// Main fused kernel: one block per node i
// ---------------------------------------------------------------------------
__global__ __launch_bounds__(256, 2)
void egnn_main(const float* __restrict__ x,  const float* __restrict__ a,
               const float* __restrict__ h,  const float* __restrict__ We1,
               const float* __restrict__ We2, const float* __restrict__ be2,
               const float* __restrict__ Wx1, const float* __restrict__ bx1,
               const float* __restrict__ Wx2, const float* __restrict__ bx2,
               const float* __restrict__ Wh1, const float* __restrict__ bh1,
               const float* __restrict__ Wh2, const float* __restrict__ bh2,
               float* __restrict__ out) {
    extern __shared__ float dyn[];
    float* We2s = dyn;                 // 4096
    float* Wx1s = dyn + 4096;          // 4096
    float* T    = dyn + 8192;          // 128*68 : silu(pre)
    float* Mw   = dyn + 8192 + TJ * TSTR;  // 128*68 : m = silu(T@We2+be2)

    __shared__ float peis[64], wd2s[64], was[64], be2s[64], bx1s[64], wx2s[64];
    __shared__ float his[64], m_is[64];
    __shared__ float dfx[TJ], dfy[TJ], dfz[TJ], d2s[TJ], a_s[TJ];
    __shared__ float Mpart[8][64];
    __shared__ float hh[64];
    __shared__ float xaccs[3], xi3[3];
    __shared__ float bx2s;

    const int tid  = threadIdx.x;
    const int i    = blockIdx.x;
    const int lane = tid & 31;
    const int cg   = tid & 7;    // col group: owns cols {cg*4..+3, cg*4+32..+35}
    const int rg   = tid >> 3;   // base row; thread owns rows {rg, rg+32, rg+64, rg+96}
    const int wid  = tid >> 5;

    // weights -> shared
    for (int idx = tid; idx < 1024; idx += 256) {
        ((float4*)We2s)[idx] = ((const float4*)We2)[idx];
        ((float4*)Wx1s)[idx] = ((const float4*)Wx1)[idx];
    }
    if (tid < 64) {
        peis[tid] = g_pei[i * 64 + tid];
        wd2s[tid] = We1[128 * 64 + tid];
        was[tid]  = We1[129 * 64 + tid];
        be2s[tid] = be2[tid];
        bx1s[tid] = bx1[tid];
        wx2s[tid] = Wx2[tid];
        his[tid]  = h[i * 64 + tid];
        m_is[tid] = 0.f;
    }
    if (tid < 3) { xi3[tid] = x[i * 3 + tid]; xaccs[tid] = 0.f; }
    if (tid == 0) bx2s = bx2[0];
    __syncthreads();

    const float xix = xi3[0], xiy = xi3[1], xiz = xi3[2];
    float xax = 0.f, xay = 0.f, xaz = 0.f;

    // phase-A constants (per-thread float4 over the 64 hidden channels)
    const int c4  = tid & 15;
    const int jst = tid >> 4;
    const float4 pe4 = ((float4*)peis)[c4];
    const float4 wd4 = ((float4*)wd2s)[c4];
    const float4 wa4 = ((float4*)was)[c4];

    // split-column bases for epilogues
    const int c0 = cg * 4;        // first 4 owned cols
    const int c1 = cg * 4 + 32;   // second 4 owned cols

    // prefetch registers for tile 0 (global loads issued well before use)
    float pf_x0 = 0.f, pf_x1 = 0.f, pf_x2 = 0.f, pf_a = 0.f;
    if (tid < TJ) {
        pf_x0 = x[tid * 3 + 0];
        pf_x1 = x[tid * 3 + 1];
        pf_x2 = x[tid * 3 + 2];
        pf_a  = a[(size_t)i * MN + tid];
    }

    for (int jt = 0; jt < MN / TJ; jt++) {
        const int j0 = jt * TJ;
        __syncthreads();  // prior tile fully consumed (Mw, diffs)

        // stage-1: commit prefetched coords/a, then issue next tile's loads
        if (tid < TJ) {
            const float dx = xix - pf_x0;
            const float dy = xiy - pf_x1;
            const float dz = xiz - pf_x2;
            dfx[tid] = dx; dfy[tid] = dy; dfz[tid] = dz;
            d2s[tid] = dx * dx + dy * dy + dz * dz;
            a_s[tid] = pf_a;
            if (jt + 1 < MN / TJ) {
                const int jn = j0 + TJ + tid;
                pf_x0 = x[jn * 3 + 0];
                pf_x1 = x[jn * 3 + 1];
                pf_x2 = x[jn * 3 + 2];
                pf_a  = a[(size_t)i * MN + jn];
            }
        }
        __syncthreads();

        // phase A: T[jl][c] = silu(pei + pej + d2*wd2 + a*wa)  (be1 folded in pei)
        for (int jl = jst; jl < TJ; jl += 16) {
            const float4 pj = ((const float4*)(g_pej + (size_t)(j0 + jl) * 64))[c4];
            const float d2v = d2s[jl], av = a_s[jl];
            float4 v;
            v.x = fsilu(pe4.x + pj.x + d2v * wd4.x + av * wa4.x);
            v.y = fsilu(pe4.y + pj.y + d2v * wd4.y + av * wa4.y);
            v.z = fsilu(pe4.z + pj.z + d2v * wd4.z + av * wa4.z);
            v.w = fsilu(pe4.w + pj.w + d2v * wd4.w + av * wa4.w);
            *(float4*)(T + jl * TSTR + c4 * 4) = v;
        }
        __syncthreads();

        // phase B: Mw = silu(T @ We2 + be2); fold per-column row-sums (m_i)
        {
            float2 acc[4][4];
            gemm_tile(T + rg * TSTR, We2s, cg, acc);

            float csum[8];
#pragma unroll
            for (int c8 = 0; c8 < 8; c8++) csum[c8] = 0.f;
#pragma unroll
            for (int q = 0; q < 4; q++) {
                const int jl = rg + 32 * q;
                const float msk = (j0 + jl != i) ? 1.f : 0.f;
                float4 v0, v1;
                v0.x = fsilu(acc[q][0].x + be2s[c0 + 0]);
                v0.y = fsilu(acc[q][0].y + be2s[c0 + 1]);
                v0.z = fsilu(acc[q][1].x + be2s[c0 + 2]);
                v0.w = fsilu(acc[q][1].y + be2s[c0 + 3]);
                v1.x = fsilu(acc[q][2].x + be2s[c1 + 0]);
                v1.y = fsilu(acc[q][2].y + be2s[c1 + 1]);
                v1.z = fsilu(acc[q][3].x + be2s[c1 + 2]);
                v1.w = fsilu(acc[q][3].y + be2s[c1 + 3]);
                *(float4*)(Mw + jl * TSTR + c0) = v0;
                *(float4*)(Mw + jl * TSTR + c1) = v1;
                csum[0] += msk * v0.x; csum[1] += msk * v0.y;
                csum[2] += msk * v0.z; csum[3] += msk * v0.w;
                csum[4] += msk * v1.x; csum[5] += msk * v1.y;
                csum[6] += msk * v1.z; csum[7] += msk * v1.w;
            }
            // reduce over row-groups within warp (lane bits 3,4)
#pragma unroll
            for (int c8 = 0; c8 < 8; c8++) {
                csum[c8] += __shfl_xor_sync(0xffffffffu, csum[c8], 8);
                csum[c8] += __shfl_xor_sync(0xffffffffu, csum[c8], 16);
            }
            if (lane < 8) {   // lane == cg here
#pragma unroll
                for (int t = 0; t < 4; t++) {
                    Mpart[wid][c0 + t] = csum[t];
                    Mpart[wid][c1 + t] = csum[4 + t];
                }
            }
        }
        __syncthreads();
        if (tid < 64) {
            float s = m_is[tid];
#pragma unroll
            for (int w = 0; w < 8; w++) s += Mpart[w][tid];
            m_is[tid] = s;
        }

        // phase C: spre = Mw @ Wx1 + bx1 ; s = silu(spre)@Wx2 + bx2 ; xacc += diff*s
        {
            float2 acc[4][4];
            gemm_tile(Mw + rg * TSTR, Wx1s, cg, acc);

            float sq[4];
#pragma unroll
            for (int q = 0; q < 4; q++) {
                float t = 0.f;
                t += fsilu(acc[q][0].x + bx1s[c0 + 0]) * wx2s[c0 + 0];
                t += fsilu(acc[q][0].y + bx1s[c0 + 1]) * wx2s[c0 + 1];
                t += fsilu(acc[q][1].x + bx1s[c0 + 2]) * wx2s[c0 + 2];
                t += fsilu(acc[q][1].y + bx1s[c0 + 3]) * wx2s[c0 + 3];
                t += fsilu(acc[q][2].x + bx1s[c1 + 0]) * wx2s[c1 + 0];
                t += fsilu(acc[q][2].y + bx1s[c1 + 1]) * wx2s[c1 + 1];
                t += fsilu(acc[q][3].x + bx1s[c1 + 2]) * wx2s[c1 + 2];
                t += fsilu(acc[q][3].y + bx1s[c1 + 3]) * wx2s[c1 + 3];
                t += __shfl_xor_sync(0xffffffffu, t, 1);
                t += __shfl_xor_sync(0xffffffffu, t, 2);
                t += __shfl_xor_sync(0xffffffffu, t, 4);
                sq[q] = t;
            }
            if (cg == 0) {
#pragma unroll
                for (int q = 0; q < 4; q++) {
                    const int jl = rg + 32 * q;
                    if (j0 + jl != i) {
                        const float sv = sq[q] + bx2s;
                        xax += dfx[jl] * sv;
                        xay += dfy[jl] * sv;
                        xaz += dfz[jl] * sv;
                    }
                }
            }
        }
    }

    // reduce xacc across block
#pragma unroll
    for (int off = 16; off; off >>= 1) {
        xax += __shfl_xor_sync(0xffffffffu, xax, off);
        xay += __shfl_xor_sync(0xffffffffu, xay, off);
        xaz += __shfl_xor_sync(0xffffffffu, xaz, off);
    }
    if (lane == 0) {
        atomicAdd(&xaccs[0], xax);
        atomicAdd(&xaccs[1], xay);
        atomicAdd(&xaccs[2], xaz);
    }
    __syncthreads();

    // phi_h: h_new = silu([h_i, m_i] @ Wh1 + bh1) @ Wh2 + bh2
    {
        const int c = tid & 63, q = tid >> 6;
        float acc = 0.f;
#pragma unroll 8
        for (int kk = 0; kk < 32; kk++) {
            const int k = q * 32 + kk;
            const float in = (k < 64) ? his[k] : m_is[k - 64];
            acc += in * Wh1[k * 64 + c];
        }
        Mpart[q][c] = acc;
        __syncthreads();
        if (tid < 64) {
            float v = bh1[tid];
#pragma unroll
            for (int w = 0; w < 4; w++) v += Mpart[w][tid];
            hh[tid] = fsilu(v);
        }
        __syncthreads();
        acc = 0.f;
#pragma unroll
        for (int kk = 0; kk < 16; kk++) {
            const int k = q * 16 + kk;
            acc += hh[k] * Wh2[k * 64 + c];
        }
        Mpart[q][c] = acc;
        __syncthreads();
        if (tid < 64) {
            float v = bh2[tid];
#pragma unroll
            for (int w = 0; w < 4; w++) v += Mpart[w][tid];
            out[3 * MN + i * 64 + tid] = v;
        }
    }
    if (tid < 3)
        out[i * 3 + tid] = xi3[tid] + (1.0f / (float)(MN - 1)) * xaccs[tid];
}

// ---------------------------------------------------------------------------
extern "C" void kernel_launch(void* const* d_in, const int* in_sizes, int n_in,
                              void* d_out, int out_size) {
    const float* x   = (const float*)d_in[0];
    const float* a   = (const float*)d_in[1];
    const float* h   = (const float*)d_in[2];
    const float* We1 = (const float*)d_in[3];
    const float* be1 = (const float*)d_in[4];
    const float* We2 = (const float*)d_in[5];
    const float* be2 = (const float*)d_in[6];
    const float* Wx1 = (const float*)d_in[7];
    const float* bx1 = (const float*)d_in[8];
    const float* Wx2 = (const float*)d_in[9];
    const float* bx2 = (const float*)d_in[10];
    const float* Wh1 = (const float*)d_in[11];
    const float* bh1 = (const float*)d_in[12];
    const float* Wh2 = (const float*)d_in[13];
    const float* bh2 = (const float*)d_in[14];
    float* out = (float*)d_out;

    cudaFuncSetAttribute(egnn_main, cudaFuncAttributeMaxDynamicSharedMemorySize, DYN_BYTES);

    pre_kernel<<<MN / 4, 256>>>(h, We1, be1);
    egnn_main<<<MN, 256, DYN_BYTES>>>(x, a, h, We1, We2, be2, Wx1, bx1,
                                      Wx2, bx2, Wh1, bh1, Wh2, bh2, out);
}

// round 17
// speedup vs baseline: 1.5621x; 1.5621x over previous
#include <cuda_runtime.h>

#define MN   1024
#define HID  64
#define TJ   128
#define NT   128         // threads per block (main kernel)
#define TSTR 68          // row stride (floats): 64 + 4 pad ; 272 B = 17*16 -> float4-aligned rows
#define DYN_FLOATS (4096 + 4096 + TJ*TSTR + TJ*TSTR)
#define DYN_BYTES  (DYN_FLOATS * 4)

__device__ float g_pei[MN * HID];   // includes be1
__device__ float g_pej[MN * HID];

__device__ __forceinline__ float fsilu(float v) {
    return __fdividef(v, 1.0f + __expf(-v));
}

// ---- packed fp32x2 helpers (sm_103a) --------------------------------------
union F2U { unsigned long long u; float2 f; };

__device__ __forceinline__ unsigned long long ffma2(unsigned long long a,
                                                    unsigned long long b,
                                                    unsigned long long c) {
    unsigned long long d;
    asm("fma.rn.f32x2 %0, %1, %2, %3;" : "=l"(d) : "l"(a), "l"(b), "l"(c));
    return d;
}
__device__ __forceinline__ unsigned long long pack2(float v) {
    unsigned long long d;
    asm("mov.b64 %0, {%1, %1};" : "=l"(d) : "f"(v));
    return d;
}

// ---------------------------------------------------------------------------
// Precompute: pei[i][c] = be1[c] + sum_k h[i][k]*We1[k][c]
//             pej[j][c] =          sum_k h[j][k]*We1[64+k][c]
// ---------------------------------------------------------------------------
__global__ void pre_kernel(const float* __restrict__ h,
                           const float* __restrict__ We1,
                           const float* __restrict__ be1) {
    __shared__ float hs[4][64];
    const int tid = threadIdx.x;
    const int rr  = tid >> 6;
    const int c   = tid & 63;
    const int row = blockIdx.x * 4 + rr;
    hs[rr][c] = h[row * 64 + c];
    __syncthreads();
    float ai = be1[c];
    float aj = 0.f;
#pragma unroll 8
    for (int k = 0; k < 64; k++) {
        const float hv = hs[rr][k];
        ai += hv * We1[k * 64 + c];
        aj += hv * We1[(64 + k) * 64 + c];
    }
    g_pei[row * 64 + c] = ai;
    g_pej[row * 64 + c] = aj;
}

// 128x64x64 GEMM micro-kernel, packed f32x2 FMA, 8x8 outputs per thread.
// Thread owns rows {rg + 16t, t=0..7} (strided -> conflict-free A LDS)
// and SPLIT column set {cg*4..+3, cg*4+32..+35} (conflict-free B LDS + stores):
//   acc[q][0] = cols (4cg, 4cg+1)     acc[q][1] = (4cg+2, 4cg+3)
//   acc[q][2] = (4cg+32, 4cg+33)      acc[q][3] = (4cg+34, 4cg+35)
__device__ __forceinline__ void gemm_tile(const float* __restrict__ Arow0,  // A + rg*TSTR
                                          const float* __restrict__ Bs,     // [64][64] row-major
                                          int cg, float2 acc[8][4]) {
    unsigned long long a2[8][4];
#pragma unroll
    for (int q = 0; q < 8; q++)
#pragma unroll
        for (int p = 0; p < 4; p++) a2[q][p] = 0ull;

#pragma unroll 2
    for (int k4 = 0; k4 < 16; k4++) {
        const int k = k4 * 4;
        // A: 8 rows (stride 16*TSTR) x 4 k-values, via LDS.128 (broadcast per 8 lanes)
        float4 af[8];
#pragma unroll
        for (int t = 0; t < 8; t++)
            af[t] = *(const float4*)(Arow0 + t * 16 * TSTR + k);
#pragma unroll
        for (int kk = 0; kk < 4; kk++) {
            unsigned long long ap[8];
#pragma unroll
            for (int t = 0; t < 8; t++) ap[t] = pack2(((const float*)&af[t])[kk]);
            const ulonglong2 b0 = *(const ulonglong2*)(Bs + (k + kk) * 64 + cg * 4);
            const ulonglong2 b1 = *(const ulonglong2*)(Bs + (k + kk) * 64 + cg * 4 + 32);
            const unsigned long long bv[4] = {b0.x, b0.y, b1.x, b1.y};
#pragma unroll
            for (int q = 0; q < 8; q++)
#pragma unroll
                for (int p = 0; p < 4; p++) a2[q][p] = ffma2(ap[q], bv[p], a2[q][p]);
        }
    }
#pragma unroll
    for (int q = 0; q < 8; q++)
#pragma unroll
        for (int p = 0; p < 4; p++) {
            F2U u; u.u = a2[q][p];
            acc[q][p] = u.f;
        }
}

// ---------------------------------------------------------------------------
// Main fused kernel: one block per node i, 128 threads
// ---------------------------------------------------------------------------
__global__ __launch_bounds__(NT, 2)
void egnn_main(const float* __restrict__ x,  const float* __restrict__ a,
               const float* __restrict__ h,  const float* __restrict__ We1,
               const float* __restrict__ We2, const float* __restrict__ be2,
               const float* __restrict__ Wx1, const float* __restrict__ bx1,
               const float* __restrict__ Wx2, const float* __restrict__ bx2,
               const float* __restrict__ Wh1, const float* __restrict__ bh1,
               const float* __restrict__ Wh2, const float* __restrict__ bh2,
               float* __restrict__ out) {
    extern __shared__ float dyn[];
    float* We2s = dyn;                 // 4096
    float* Wx1s = dyn + 4096;          // 4096
    float* T    = dyn + 8192;          // 128*68 : silu(pre)
    float* Mw   = dyn + 8192 + TJ * TSTR;  // 128*68 : m = silu(T@We2+be2)

    __shared__ float peis[64], wd2s[64], was[64], be2s[64], bx1s[64], wx2s[64];
    __shared__ float his[64], m_is[64];
    __shared__ float dfx[TJ], dfy[TJ], dfz[TJ], d2s[TJ], a_s[TJ];
    __shared__ float Mpart[4][64];
    __shared__ float hh[64];
    __shared__ float xaccs[3], xi3[3];
    __shared__ float bx2s;

    const int tid  = threadIdx.x;
    const int i    = blockIdx.x;
    const int lane = tid & 31;
    const int cg   = tid & 7;    // col group: owns cols {cg*4..+3, cg*4+32..+35}
    const int rg   = tid >> 3;   // base row (0..15); owns rows {rg + 16t, t=0..7}
    const int wid  = tid >> 5;   // 0..3

    // weights -> shared
    for (int idx = tid; idx < 1024; idx += NT) {
        ((float4*)We2s)[idx] = ((const float4*)We2)[idx];
        ((float4*)Wx1s)[idx] = ((const float4*)Wx1)[idx];
    }
    if (tid < 64) {
        peis[tid] = g_pei[i * 64 + tid];
        wd2s[tid] = We1[128 * 64 + tid];
        was[tid]  = We1[129 * 64 + tid];
        be2s[tid] = be2[tid];
        bx1s[tid] = bx1[tid];
        wx2s[tid] = Wx2[tid];
        his[tid]  = h[i * 64 + tid];
        m_is[tid] = 0.f;
    }
    if (tid < 3) { xi3[tid] = x[i * 3 + tid]; xaccs[tid] = 0.f; }
    if (tid == 0) bx2s = bx2[0];
    __syncthreads();

    const float xix = xi3[0], xiy = xi3[1], xiz = xi3[2];
    float xax = 0.f, xay = 0.f, xaz = 0.f;

    // phase-A constants (per-thread float4 over the 64 hidden channels)
    const int c4  = tid & 15;
    const int jst = tid >> 4;    // 0..7
    const float4 pe4 = ((float4*)peis)[c4];
    const float4 wd4 = ((float4*)wd2s)[c4];
    const float4 wa4 = ((float4*)was)[c4];

    // split-column bases for epilogues
    const int c0 = cg * 4;        // first 4 owned cols
    const int c1 = cg * 4 + 32;   // second 4 owned cols

    // prefetch registers for tile 0 (global loads issued well before use)
    float pf_x0 = x[tid * 3 + 0];
    float pf_x1 = x[tid * 3 + 1];
    float pf_x2 = x[tid * 3 + 2];
    float pf_a  = a[(size_t)i * MN + tid];

    for (int jt = 0; jt < MN / TJ; jt++) {
        const int j0 = jt * TJ;
        __syncthreads();  // prior tile fully consumed (Mw, diffs)

        // stage-1: commit prefetched coords/a, then issue next tile's loads
        {
            const float dx = xix - pf_x0;
            const float dy = xiy - pf_x1;
            const float dz = xiz - pf_x2;
            dfx[tid] = dx; dfy[tid] = dy; dfz[tid] = dz;
            d2s[tid] = dx * dx + dy * dy + dz * dz;
            a_s[tid] = pf_a;
            if (jt + 1 < MN / TJ) {
                const int jn = j0 + TJ + tid;
                pf_x0 = x[jn * 3 + 0];
                pf_x1 = x[jn * 3 + 1];
                pf_x2 = x[jn * 3 + 2];
                pf_a  = a[(size_t)i * MN + jn];
            }
        }
        __syncthreads();

        // phase A: T[jl][c] = silu(pei + pej + d2*wd2 + a*wa)  (be1 folded in pei)
        for (int jl = jst; jl < TJ; jl += 8) {
            const float4 pj = ((const float4*)(g_pej + (size_t)(j0 + jl) * 64))[c4];
            const float d2v = d2s[jl], av = a_s[jl];
            float4 v;
            v.x = fsilu(pe4.x + pj.x + d2v * wd4.x + av * wa4.x);
            v.y = fsilu(pe4.y + pj.y + d2v * wd4.y + av * wa4.y);
            v.z = fsilu(pe4.z + pj.z + d2v * wd4.z + av * wa4.z);
            v.w = fsilu(pe4.w + pj.w + d2v * wd4.w + av * wa4.w);
            *(float4*)(T + jl * TSTR + c4 * 4) = v;
        }
        __syncthreads();

        // phase B: Mw = silu(T @ We2 + be2); fold per-column row-sums (m_i)
        {
            float2 acc[8][4];
            gemm_tile(T + rg * TSTR, We2s, cg, acc);

            float csum[8];
#pragma unroll
            for (int c8 = 0; c8 < 8; c8++) csum[c8] = 0.f;
#pragma unroll
            for (int q = 0; q < 8; q++) {
                const int jl = rg + 16 * q;
                const float msk = (j0 + jl != i) ? 1.f : 0.f;
                float4 v0, v1;
                v0.x = fsilu(acc[q][0].x + be2s[c0 + 0]);
                v0.y = fsilu(acc[q][0].y + be2s[c0 + 1]);
                v0.z = fsilu(acc[q][1].x + be2s[c0 + 2]);
                v0.w = fsilu(acc[q][1].y + be2s[c0 + 3]);
                v1.x = fsilu(acc[q][2].x + be2s[c1 + 0]);
                v1.y = fsilu(acc[q][2].y + be2s[c1 + 1]);
                v1.z = fsilu(acc[q][3].x + be2s[c1 + 2]);
                v1.w = fsilu(acc[q][3].y + be2s[c1 + 3]);
                *(float4*)(Mw + jl * TSTR + c0) = v0;
                *(float4*)(Mw + jl * TSTR + c1) = v1;
                csum[0] += msk * v0.x; csum[1] += msk * v0.y;
                csum[2] += msk * v0.z; csum[3] += msk * v0.w;
                csum[4] += msk * v1.x; csum[5] += msk * v1.y;
                csum[6] += msk * v1.z; csum[7] += msk * v1.w;
            }
            // reduce over the 4 rg values within warp (lane bits 3,4)
#pragma unroll
            for (int c8 = 0; c8 < 8; c8++) {
                csum[c8] += __shfl_xor_sync(0xffffffffu, csum[c8], 8);
                csum[c8] += __shfl_xor_sync(0xffffffffu, csum[c8], 16);
            }
            if (lane < 8) {   // lane == cg here
#pragma unroll
                for (int t = 0; t < 4; t++) {
                    Mpart[wid][c0 + t] = csum[t];
                    Mpart[wid][c1 + t] = csum[4 + t];
                }
            }
        }
        __syncthreads();
        if (tid < 64) {
            float s = m_is[tid];
#pragma unroll
            for (int w = 0; w < 4; w++) s += Mpart[w][tid];
            m_is[tid] = s;
        }

        // phase C: spre = Mw @ Wx1 + bx1 ; s = silu(spre)@Wx2 + bx2 ; xacc += diff*s
        {
            float2 acc[8][4];
            gemm_tile(Mw + rg * TSTR, Wx1s, cg, acc);

            float sq[8];
#pragma unroll
            for (int q = 0; q < 8; q++) {
                float t = 0.f;
                t += fsilu(acc[q][0].x + bx1s[c0 + 0]) * wx2s[c0 + 0];
                t += fsilu(acc[q][0].y + bx1s[c0 + 1]) * wx2s[c0 + 1];
                t += fsilu(acc[q][1].x + bx1s[c0 + 2]) * wx2s[c0 + 2];
                t += fsilu(acc[q][1].y + bx1s[c0 + 3]) * wx2s[c0 + 3];
                t += fsilu(acc[q][2].x + bx1s[c1 + 0]) * wx2s[c1 + 0];
                t += fsilu(acc[q][2].y + bx1s[c1 + 1]) * wx2s[c1 + 1];
                t += fsilu(acc[q][3].x + bx1s[c1 + 2]) * wx2s[c1 + 2];
                t += fsilu(acc[q][3].y + bx1s[c1 + 3]) * wx2s[c1 + 3];
                t += __shfl_xor_sync(0xffffffffu, t, 1);
                t += __shfl_xor_sync(0xffffffffu, t, 2);
                t += __shfl_xor_sync(0xffffffffu, t, 4);
                sq[q] = t;
            }
            if (cg == 0) {
#pragma unroll
                for (int q = 0; q < 8; q++) {
                    const int jl = rg + 16 * q;
                    if (j0 + jl != i) {
                        const float sv = sq[q] + bx2s;
                        xax += dfx[jl] * sv;
                        xay += dfy[jl] * sv;
                        xaz += dfz[jl] * sv;
                    }
                }
            }
        }
    }

    // reduce xacc across block
#pragma unroll
    for (int off = 16; off; off >>= 1) {
        xax += __shfl_xor_sync(0xffffffffu, xax, off);
        xay += __shfl_xor_sync(0xffffffffu, xay, off);
        xaz += __shfl_xor_sync(0xffffffffu, xaz, off);
    }
    if (lane == 0) {
        atomicAdd(&xaccs[0], xax);
        atomicAdd(&xaccs[1], xay);
        atomicAdd(&xaccs[2], xaz);
    }
    __syncthreads();

    // phi_h: h_new = silu([h_i, m_i] @ Wh1 + bh1) @ Wh2 + bh2
    {
        const int c = tid & 63, q = tid >> 6;   // q = 0..1
        float acc = 0.f;
#pragma unroll 8
        for (int kk = 0; kk < 64; kk++) {
            const int k = q * 64 + kk;
            const float in = (k < 64) ? his[k] : m_is[k - 64];
            acc += in * Wh1[k * 64 + c];
        }
        Mpart[q][c] = acc;
        __syncthreads();
        if (tid < 64) {
            float v = bh1[tid];
            v += Mpart[0][tid] + Mpart[1][tid];
            hh[tid] = fsilu(v);
        }
        __syncthreads();
        acc = 0.f;
#pragma unroll
        for (int kk = 0; kk < 32; kk++) {
            const int k = q * 32 + kk;
            acc += hh[k] * Wh2[k * 64 + c];
        }
        Mpart[q][c] = acc;
        __syncthreads();
        if (tid < 64) {
            float v = bh2[tid];
            v += Mpart[0][tid] + Mpart[1][tid];
            out[3 * MN + i * 64 + tid] = v;
        }
    }
    if (tid < 3)
        out[i * 3 + tid] = xi3[tid] + (1.0f / (float)(MN - 1)) * xaccs[tid];
}

// ---------------------------------------------------------------------------
extern "C" void kernel_launch(void* const* d_in, const int* in_sizes, int n_in,
                              void* d_out, int out_size) {
    const float* x   = (const float*)d_in[0];
    const float* a   = (const float*)d_in[1];
    const float* h   = (const float*)d_in[2];
    const float* We1 = (const float*)d_in[3];
    const float* be1 = (const float*)d_in[4];
    const float* We2 = (const float*)d_in[5];
    const float* be2 = (const float*)d_in[6];
    const float* Wx1 = (const float*)d_in[7];
    const float* bx1 = (const float*)d_in[8];
    const float* Wx2 = (const float*)d_in[9];
    const float* bx2 = (const float*)d_in[10];
    const float* Wh1 = (const float*)d_in[11];
    const float* bh1 = (const float*)d_in[12];
    const float* Wh2 = (const float*)d_in[13];
    const float* bh2 = (const float*)d_in[14];
    float* out = (float*)d_out;

    cudaFuncSetAttribute(egnn_main, cudaFuncAttributeMaxDynamicSharedMemorySize, DYN_BYTES);

    pre_kernel<<<MN / 4, 256>>>(h, We1, be1);
    egnn_main<<<MN, NT, DYN_BYTES>>>(x, a, h, We1, We2, be2, Wx1, bx1,
                                     Wx2, bx2, Wh1, bh1, Wh2, bh2, out);
}